// round 6
// baseline (speedup 1.0000x reference)
#include <cuda_runtime.h>
#include <math.h>

#define T_ 256
#define B_ 32
#define E_ 256
#define H_ 256
#define K_ 48
#define M_ (T_*B_)      /* 8192 rows (t*B+b) */
#define G4_ 1024        /* 4*H */
#define NARR_ 512       /* barrier arrivals: 4 warps x 128 blocks */

typedef unsigned long long ull;

// ---------------- f32x2 packed helpers (FFMA2 path, sm_100+) ----------------
__device__ __forceinline__ ull ffma2(ull a, ull b, ull c) {
    ull d; asm("fma.rn.f32x2 %0, %1, %2, %3;" : "=l"(d) : "l"(a), "l"(b), "l"(c)); return d;
}
__device__ __forceinline__ ull add2(ull a, ull b) {
    ull d; asm("add.rn.f32x2 %0, %1, %2;" : "=l"(d) : "l"(a), "l"(b)); return d;
}
__device__ __forceinline__ ull pk2(float lo, float hi) {
    ull r; asm("mov.b64 %0, {%1, %2};" : "=l"(r) : "f"(lo), "f"(hi)); return r;
}
__device__ __forceinline__ void upk2(ull v, float& lo, float& hi) {
    asm("mov.b64 {%0, %1}, %2;" : "=f"(lo), "=f"(hi) : "l"(v));
}

// ---------------- scratch (device globals; no allocs allowed) ----------------
__device__ float g_emb [M_*E_];           // embedded input, (t*B+b, 256)
__device__ float g_xcat[M_*512];          // concat hf|hb,  (t*B+b, 512)
__device__ float g_pref[(size_t)M_*G4_];  // pre-gates fwd
__device__ float g_preb[(size_t)M_*G4_];  // pre-gates bwd
__device__ float g_emit[M_*K_];           // emit, (t*B+b, 48)
__device__ float g_h   [2*2*2*H_*B_];     // [layer][buf][dir][u*32+b]
__device__ int   g_bar [2*2*T_];          // [layer][dir][step]
__device__ float g_part[B_];

// ---------------- init: zero h state + barriers each launch ----------------
__global__ void init_kernel() {
    int tid = blockIdx.x * blockDim.x + threadIdx.x;
    int n = blockDim.x * gridDim.x;
    for (int i = tid; i < 2*2*2*H_*B_; i += n) g_h[i] = 0.f;
    for (int i = tid; i < 2*2*T_; i += n) g_bar[i] = 0;
}

// ---------------- embedding gather + mask output ----------------
__global__ void embed_kernel(const int* __restrict__ sentence,
                             const float* __restrict__ embed,
                             float* __restrict__ out_mask) {
    int m = blockIdx.x;             // m = t*B + b
    int t = m >> 5, b = m & 31;
    int tok = sentence[b * T_ + t];
    const float4* src = (const float4*)(embed + (size_t)tok * E_);
    float4* dst = (float4*)(g_emb + (size_t)m * E_);
    dst[threadIdx.x] = src[threadIdx.x];        // 64 threads * float4 = 256
    if (threadIdx.x == 0) out_mask[b * T_ + t] = (tok != 0) ? 1.f : 0.f;
}

// ---------------- SGEMM (FFMA2): C[M,1024] = A[M,Kd] @ W[1024,Kd]^T + bias ---
// grid(16, 64, 2), block 256. BM=128, BN=64, BK=8, thread tile 8x4.
__global__ void gemm_pre(const float* __restrict__ A,
                         const float* __restrict__ Wf, const float* __restrict__ Wb,
                         const float* __restrict__ biasf, const float* __restrict__ biasb,
                         float* __restrict__ Cf, float* __restrict__ Cb, int Kd) {
    __shared__ float As[8][128];
    __shared__ float Bs[8][64];
    const float* W    = blockIdx.z ? Wb : Wf;
    const float* bias = blockIdx.z ? biasb : biasf;
    float*       C    = blockIdx.z ? Cb : Cf;

    int tid = threadIdx.x;
    int row0 = blockIdx.y * 128;
    int col0 = blockIdx.x * 64;
    int tr = tid >> 4, tc = tid & 15;      // 16x16 thread grid
    int ar = tid >> 1, ak = (tid & 1) * 4; // A load: 128 rows x 8k
    int wc = tid >> 2, wk = (tid & 3) * 2; // W load: 64 rows x 8k
    ull acc2[4][4];                        // [row-pair][col]
#pragma unroll
    for (int p = 0; p < 4; p++)
#pragma unroll
        for (int j = 0; j < 4; j++) acc2[p][j] = 0ull;

    for (int k0 = 0; k0 < Kd; k0 += 8) {
        float4 av = *(const float4*)(A + (size_t)(row0 + ar) * Kd + k0 + ak);
        float2 wv = *(const float2*)(W + (size_t)(col0 + wc) * Kd + k0 + wk);
        As[ak+0][ar] = av.x; As[ak+1][ar] = av.y; As[ak+2][ar] = av.z; As[ak+3][ar] = av.w;
        Bs[wk+0][wc] = wv.x; Bs[wk+1][wc] = wv.y;
        __syncthreads();
#pragma unroll
        for (int k = 0; k < 8; ++k) {
            ulonglong2 a01 = *(const ulonglong2*)&As[k][tr*8];     // row pairs (0,1),(2,3)
            ulonglong2 a23 = *(const ulonglong2*)&As[k][tr*8+4];   // (4,5),(6,7)
            float4 b4 = *(const float4*)&Bs[k][tc*4];
            ull bd0 = pk2(b4.x, b4.x), bd1 = pk2(b4.y, b4.y);
            ull bd2 = pk2(b4.z, b4.z), bd3 = pk2(b4.w, b4.w);
            acc2[0][0]=ffma2(a01.x,bd0,acc2[0][0]); acc2[0][1]=ffma2(a01.x,bd1,acc2[0][1]);
            acc2[0][2]=ffma2(a01.x,bd2,acc2[0][2]); acc2[0][3]=ffma2(a01.x,bd3,acc2[0][3]);
            acc2[1][0]=ffma2(a01.y,bd0,acc2[1][0]); acc2[1][1]=ffma2(a01.y,bd1,acc2[1][1]);
            acc2[1][2]=ffma2(a01.y,bd2,acc2[1][2]); acc2[1][3]=ffma2(a01.y,bd3,acc2[1][3]);
            acc2[2][0]=ffma2(a23.x,bd0,acc2[2][0]); acc2[2][1]=ffma2(a23.x,bd1,acc2[2][1]);
            acc2[2][2]=ffma2(a23.x,bd2,acc2[2][2]); acc2[2][3]=ffma2(a23.x,bd3,acc2[2][3]);
            acc2[3][0]=ffma2(a23.y,bd0,acc2[3][0]); acc2[3][1]=ffma2(a23.y,bd1,acc2[3][1]);
            acc2[3][2]=ffma2(a23.y,bd2,acc2[3][2]); acc2[3][3]=ffma2(a23.y,bd3,acc2[3][3]);
        }
        __syncthreads();
    }
#pragma unroll
    for (int p = 0; p < 4; p++) {
        int r0 = row0 + tr * 8 + 2 * p;
#pragma unroll
        for (int j = 0; j < 4; j++) {
            int c = col0 + tc * 4 + j;
            float lo, hi; upk2(acc2[p][j], lo, hi);
            float bv = bias[c];
            C[(size_t)r0 * G4_ + c]       = lo + bv;
            C[(size_t)(r0+1) * G4_ + c]   = hi + bv;
        }
    }
}

// ---------------- LSTM helpers ----------------
__device__ __forceinline__ void pollwait(int* p) {
    int v;
    asm volatile("ld.acquire.gpu.global.s32 %0, [%1];" : "=r"(v) : "l"(p) : "memory");
    while (v < NARR_) {
        __nanosleep(20);
        asm volatile("ld.acquire.gpu.global.s32 %0, [%1];" : "=r"(v) : "l"(p) : "memory");
    }
}

// split-K GEMM for one direction: warp covers k in [kbase, kbase+32).
// outputs: per lane (li*4+i batches) x (gate lj, units 0&1 packed as f32x2).
// partials stored per-lane-contiguous (conflict-free STS.128).
__device__ __forceinline__ void gemm_dir(const float* __restrict__ h_sh,
                                         const ull* __restrict__ wu,
                                         ull* __restrict__ red,
                                         int warp, int lane, int li, int lj, int kbase) {
    ull a0 = 0, a1 = 0, a2 = 0, a3 = 0;
#pragma unroll 8
    for (int kk = 0; kk < 32; ++kk) {
        int k = kbase + kk;
        float4 hv = *(const float4*)(h_sh + k * 32 + li * 4);
        ull wv = wu[k * 4 + lj];
        a0 = ffma2(pk2(hv.x, hv.x), wv, a0);
        a1 = ffma2(pk2(hv.y, hv.y), wv, a1);
        a2 = ffma2(pk2(hv.z, hv.z), wv, a2);
        a3 = ffma2(pk2(hv.w, hv.w), wv, a3);
    }
    ulonglong2* rp = (ulonglong2*)(red + warp * 128 + lane * 4);
    rp[0] = make_ulonglong2(a0, a1);
    rp[1] = make_ulonglong2(a2, a3);
}

// ---------------- persistent BiLSTM layer (both directions per block) -------
// grid 128, block 256, dyn smem 98816B. Block owns 2 units x 32 batches x 2 dirs.
// Phases: gemm_f | (update_f + arrive_f) || (poll_b + load h_b) | gemm_b |
//         (update_b + arrive_b) || (poll_f + load h_f)  -- sync hidden by the
//         other direction's compute.
__global__ void __launch_bounds__(256, 1)
lstm_layer(const float* __restrict__ pre_f, const float* __restrict__ pre_b,
           const float* __restrict__ Whh_f, const float* __restrict__ Whh_b,
           const int* __restrict__ lengths, float* __restrict__ xcat,
           int* __restrict__ bar, float* __restrict__ hbase) {
    extern __shared__ float sm[];
    float* w_f  = sm;                  // [256][8]  r = gate*2 + u
    float* w_b  = sm + 2048;
    float* h_f  = sm + 4096;           // [256][32] (unit-major)
    float* h_b  = sm + 12288;
    ull*  red_f = (ull*)(sm + 20480);  // [8][128]
    ull*  red_b = (ull*)(sm + 22528);
    float* c_f  = sm + 24576;          // [64] (b*2+u)
    float* c_b  = sm + 24640;

    int tid = threadIdx.x;
    int warp = tid >> 5, lane = tid & 31;
    int li = lane >> 2, lj = lane & 3;
    int kbase = warp * 32;
    int u_base = blockIdx.x * 2;

    int grpF = (warp < 4);
    int rtid = grpF ? tid : tid - 128;   // 0..127 within role group
    int rb = rtid >> 2;                  // batch 0..31
    int rg = rtid & 3;                   // gate this thread reduced
    int x  = lane & 3;
    int ru = x;                          // unit (valid when x<2)
    int upd = (x < 2);
    int dirm = grpF ? 0 : 1;
    int lb = lane & ~3;
    int ridx = ((rb >> 2) * 4 + rg) * 4 + (rb & 3);  // gather index into red

    const float* pre_my = grpF ? pre_f : pre_b;
    float* c_my = grpF ? c_f : c_b;
    float* h_my = grpF ? h_f : h_b;
    ull*  red_my = grpF ? red_f : red_b;
    int* bar_my = bar + dirm * T_;

    // weight load (coalesced over k)
    for (int idx = tid; idx < 2048; idx += 256) {
        int r = idx >> 8, k = idx & 255;     // r = gate*2+u
        int g = r >> 1, u = r & 1;
        size_t grow = (size_t)(g * 256 + u_base + u) * 256 + k;
        w_f[k * 8 + r] = Whh_f[grow];
        w_b[k * 8 + r] = Whh_b[grow];
    }
    // h(0) = 0, c(0) = 0
    for (int i = tid; i < 8192; i += 256) { h_f[i] = 0.f; h_b[i] = 0.f; }
    if (tid < 64) { c_f[tid] = 0.f; c_b[tid] = 0.f; }

    // pre-gate register pipeline (per role group's direction)
    float pg0 = 0, pg1 = 0, pg2 = 0, pg3 = 0;
    float pgn0 = 0, pgn1 = 0, pgn2 = 0, pgn3 = 0;
    int len = 0;
    if (upd) {
        len = lengths[rb];
        int t0 = dirm ? (T_ - 1) : 0;
        const float* pp = pre_my + ((size_t)t0 * B_ + rb) * G4_ + u_base + ru;
        pg0 = __ldg(pp); pg1 = __ldg(pp + 256); pg2 = __ldg(pp + 512); pg3 = __ldg(pp + 768);
    }
    __syncthreads();

    const ull* wu_f = (const ull*)w_f;
    const ull* wu_b = (const ull*)w_b;

    for (int s = 0; s < T_; ++s) {
        // -------- PHASE 0: gemm fwd --------
        gemm_dir(h_f, wu_f, red_f, warp, lane, li, lj, kbase);
        __syncthreads();   // A: fwd partials visible

        // -------- PHASE 1: fwd update || bwd barrier+reload --------
        if (grpF) {
            ull sacc = red_f[ridx];
#pragma unroll
            for (int w = 1; w < 8; ++w) sacc = add2(sacc, red_f[w * 128 + ridx]);
            ull v0 = __shfl_sync(0xffffffffu, sacc, lb + 0);
            ull v1 = __shfl_sync(0xffffffffu, sacc, lb + 1);
            ull v2 = __shfl_sync(0xffffffffu, sacc, lb + 2);
            ull v3 = __shfl_sync(0xffffffffu, sacc, lb + 3);
            if (upd) {
                float lo, hi;
                upk2(v0, lo, hi); float gi = (ru ? hi : lo) + pg0;
                upk2(v1, lo, hi); float gf = (ru ? hi : lo) + pg1;
                upk2(v2, lo, hi); float gg = (ru ? hi : lo) + pg2;
                upk2(v3, lo, hi); float go = (ru ? hi : lo) + pg3;
                int cid = rb * 2 + ru;
                float c  = c_f[cid];
                float si = 1.f / (1.f + __expf(-gi));
                float sf = 1.f / (1.f + __expf(-gf));
                float so = 1.f / (1.f + __expf(-go));
                float c2 = sf * c + si * tanhf(gg);
                float h2 = so * tanhf(c2);
                int t = s;
                int mvalid = (t < len);
                float hold = h_f[(u_base + ru) * 32 + rb];
                if (mvalid) c_f[cid] = c2;
                hbase[(((s + 1) & 1) * 2 + 0) * (H_ * B_) + (u_base + ru) * 32 + rb]
                    = mvalid ? h2 : hold;
                xcat[((size_t)t * B_ + rb) * 512 + u_base + ru] = mvalid ? h2 : 0.f;
                if (s + 1 < T_) {
                    const float* pp = pre_f + ((size_t)(s + 1) * B_ + rb) * G4_ + u_base + ru;
                    pgn0 = __ldg(pp); pgn1 = __ldg(pp + 256);
                    pgn2 = __ldg(pp + 512); pgn3 = __ldg(pp + 768);
                }
            }
            __syncwarp();
            if (lane == 0)
                asm volatile("red.release.gpu.global.add.s32 [%0], 1;"
                             :: "l"(bar + 0 * T_ + s) : "memory");
        } else {
            if (s > 0) {
                if (lane == 0) pollwait(bar + 1 * T_ + (s - 1));
                __syncwarp();
                const float* src = hbase + ((s & 1) * 2 + 1) * (H_ * B_);
#pragma unroll
                for (int i = 0; i < 16; ++i) {
                    int off = (rtid + i * 128) * 4;
                    *(float4*)(h_b + off) = __ldcg((const float4*)(src + off));
                }
            }
        }
        __syncthreads();   // B: h_b(s) ready; red_f reads done

        // -------- PHASE 2: gemm bwd --------
        gemm_dir(h_b, wu_b, red_b, warp, lane, li, lj, kbase);
        __syncthreads();   // C: bwd partials visible

        // -------- PHASE 3: bwd update || fwd barrier+reload --------
        if (!grpF) {
            ull sacc = red_b[ridx];
#pragma unroll
            for (int w = 1; w < 8; ++w) sacc = add2(sacc, red_b[w * 128 + ridx]);
            ull v0 = __shfl_sync(0xffffffffu, sacc, lb + 0);
            ull v1 = __shfl_sync(0xffffffffu, sacc, lb + 1);
            ull v2 = __shfl_sync(0xffffffffu, sacc, lb + 2);
            ull v3 = __shfl_sync(0xffffffffu, sacc, lb + 3);
            if (upd) {
                float lo, hi;
                upk2(v0, lo, hi); float gi = (ru ? hi : lo) + pg0;
                upk2(v1, lo, hi); float gf = (ru ? hi : lo) + pg1;
                upk2(v2, lo, hi); float gg = (ru ? hi : lo) + pg2;
                upk2(v3, lo, hi); float go = (ru ? hi : lo) + pg3;
                int cid = rb * 2 + ru;
                float c  = c_b[cid];
                float si = 1.f / (1.f + __expf(-gi));
                float sf = 1.f / (1.f + __expf(-gf));
                float so = 1.f / (1.f + __expf(-go));
                float c2 = sf * c + si * tanhf(gg);
                float h2 = so * tanhf(c2);
                int t = T_ - 1 - s;
                int mvalid = (t < len);
                float hold = h_b[(u_base + ru) * 32 + rb];
                if (mvalid) c_b[cid] = c2;
                hbase[(((s + 1) & 1) * 2 + 1) * (H_ * B_) + (u_base + ru) * 32 + rb]
                    = mvalid ? h2 : hold;
                xcat[((size_t)t * B_ + rb) * 512 + 256 + u_base + ru] = mvalid ? h2 : 0.f;
                if (s + 1 < T_) {
                    const float* pp = pre_b + ((size_t)(t - 1) * B_ + rb) * G4_ + u_base + ru;
                    pgn0 = __ldg(pp); pgn1 = __ldg(pp + 256);
                    pgn2 = __ldg(pp + 512); pgn3 = __ldg(pp + 768);
                }
            }
            __syncwarp();
            if (lane == 0)
                asm volatile("red.release.gpu.global.add.s32 [%0], 1;"
                             :: "l"(bar + 1 * T_ + s) : "memory");
        } else {
            if (s + 1 < T_) {
                if (lane == 0) pollwait(bar + 0 * T_ + s);
                __syncwarp();
                const float* src = hbase + (((s + 1) & 1) * 2 + 0) * (H_ * B_);
#pragma unroll
                for (int i = 0; i < 16; ++i) {
                    int off = (rtid + i * 128) * 4;
                    *(float4*)(h_f + off) = __ldcg((const float4*)(src + off));
                }
            }
        }
        __syncthreads();   // D: h_f(s+1) ready; red_b reads done

        pg0 = pgn0; pg1 = pgn1; pg2 = pgn2; pg3 = pgn3;
    }
}

// ---------------- emit: (8192x512) @ Wout^T(48x512) + bout ----------------
// grid 256, block 256. Also writes transposed output emit (B,T,K).
__global__ void emit_kernel(const float* __restrict__ xcat, const float* __restrict__ Wout,
                            const float* __restrict__ bout, float* __restrict__ emit,
                            float* __restrict__ out_emit) {
    int tid = threadIdx.x;
    int r = tid & 31;
    int cg = tid >> 5;                 // 8 groups x 6 cols
    int m = blockIdx.x * 32 + r;
    int t = m >> 5, b = m & 31;
    const ulonglong2* A = (const ulonglong2*)(xcat + (size_t)m * 512);
    ull accA[6], accB[6];
#pragma unroll
    for (int j = 0; j < 6; ++j) { accA[j] = 0ull; accB[j] = 0ull; }
    for (int k4 = 0; k4 < 128; ++k4) {
        ulonglong2 a = A[k4];
#pragma unroll
        for (int j = 0; j < 6; ++j) {
            int col = cg * 6 + j;
            ulonglong2 w = ((const ulonglong2*)(Wout + (size_t)col * 512))[k4];
            accA[j] = ffma2(a.x, w.x, accA[j]);
            accB[j] = ffma2(a.y, w.y, accB[j]);
        }
    }
#pragma unroll
    for (int j = 0; j < 6; ++j) {
        int col = cg * 6 + j;
        float a0, a1, b0, b1;
        upk2(accA[j], a0, a1); upk2(accB[j], b0, b1);
        float v = a0 + a1 + b0 + b1 + bout[col];
        emit[(size_t)m * K_ + col] = v;
        out_emit[((size_t)b * T_ + t) * K_ + col] = v;
    }
}

// ---------------- CRF per batch: numerator + forward algorithm ----------------
// 192 threads: 4-way split over the j (previous-tag) dimension.
__global__ void crf_kernel(const float* __restrict__ emit, const int* __restrict__ tags,
                           const int* __restrict__ lengths, const float* __restrict__ start_t,
                           const float* __restrict__ end_t, const float* __restrict__ trans,
                           float* __restrict__ part) {
    __shared__ float tr_sh[K_ * K_];
    __shared__ float sc[K_];
    __shared__ float pmax[4][K_];
    __shared__ float psum[4][K_];
    __shared__ float redn[192];
    int b = blockIdx.x, tid = threadIdx.x;
    int k = tid % K_, jj = tid / K_;     // jj in 0..3
    for (int i = tid; i < K_ * K_; i += 192) tr_sh[i] = trans[i];
    int len = lengths[b];
    if (tid < K_) sc[tid] = start_t[tid] + emit[(size_t)b * K_ + tid];
    __syncthreads();
    for (int t = 1; t < len; ++t) {
        float v[12];
        float mx = -1e30f;
#pragma unroll
        for (int jx = 0; jx < 12; ++jx) {
            int j = jj * 12 + jx;
            v[jx] = sc[j] + tr_sh[j * K_ + k];
            mx = fmaxf(mx, v[jx]);
        }
        float ss = 0.f;
#pragma unroll
        for (int jx = 0; jx < 12; ++jx) ss += __expf(v[jx] - mx);
        pmax[jj][k] = mx; psum[jj][k] = ss;
        __syncthreads();
        if (jj == 0) {
            float m0 = pmax[0][k], m1 = pmax[1][k], m2 = pmax[2][k], m3 = pmax[3][k];
            float gm = fmaxf(fmaxf(m0, m1), fmaxf(m2, m3));
            float s = psum[0][k] * __expf(m0 - gm) + psum[1][k] * __expf(m1 - gm)
                    + psum[2][k] * __expf(m2 - gm) + psum[3][k] * __expf(m3 - gm);
            sc[k] = gm + __logf(s) + emit[((size_t)t * B_ + b) * K_ + k];
        }
        __syncthreads();
    }
    // numerator (pure sum over t, parallel)
    float np = 0.f;
    for (int t = tid; t < len; t += 192) {
        int tg = tags[b * T_ + t];
        float e = emit[((size_t)t * B_ + b) * K_ + tg];
        if (t == 0) np += start_t[tg] + e;
        else        np += tr_sh[tags[b * T_ + t - 1] * K_ + tg] + e;
        if (t == len - 1) np += end_t[tg];
    }
    redn[tid] = np;
    __syncthreads();
    if (tid == 0) {
        float num = 0.f;
        for (int i = 0; i < 192; ++i) num += redn[i];
        float mx = -1e30f;
        for (int kk = 0; kk < K_; ++kk) mx = fmaxf(mx, sc[kk] + end_t[kk]);
        float ss = 0.f;
        for (int kk = 0; kk < K_; ++kk) ss += __expf(sc[kk] + end_t[kk] - mx);
        float den = mx + __logf(ss);
        part[b] = num - den;
    }
}

__global__ void finalize_kernel(float* __restrict__ out_loss) {
    if (threadIdx.x == 0) {
        float s = 0.f;
        for (int i = 0; i < B_; ++i) s += g_part[i];
        out_loss[0] = s / (float)B_;
    }
}

// ---------------- host launcher ----------------
extern "C" void kernel_launch(void* const* d_in, const int* in_sizes, int n_in,
                              void* d_out, int out_size) {
    const int*   sentence = (const int*)d_in[0];
    const int*   lengths  = (const int*)d_in[1];
    const int*   tags     = (const int*)d_in[2];
    const float* embed    = (const float*)d_in[3];
    const float* Wih_0f = (const float*)d_in[4];
    const float* Whh_0f = (const float*)d_in[5];
    const float* b_0f   = (const float*)d_in[6];
    const float* Wih_0b = (const float*)d_in[7];
    const float* Whh_0b = (const float*)d_in[8];
    const float* b_0b   = (const float*)d_in[9];
    const float* Wih_1f = (const float*)d_in[10];
    const float* Whh_1f = (const float*)d_in[11];
    const float* b_1f   = (const float*)d_in[12];
    const float* Wih_1b = (const float*)d_in[13];
    const float* Whh_1b = (const float*)d_in[14];
    const float* b_1b   = (const float*)d_in[15];
    const float* Wout   = (const float*)d_in[16];
    const float* bout   = (const float*)d_in[17];
    const float* start_t = (const float*)d_in[18];
    const float* end_t   = (const float*)d_in[19];
    const float* trans   = (const float*)d_in[20];

    float* out = (float*)d_out;
    float* out_emit = out;                       // (B,T,K) = 393216
    float* out_loss = out + (size_t)B_ * T_ * K_;
    float* out_mask = out_loss + 1;              // (B,T)

    const int LSTM_SMEM = 24704 * 4;             // 98816 B
    cudaFuncSetAttribute(lstm_layer, cudaFuncAttributeMaxDynamicSharedMemorySize, LSTM_SMEM);

    float *pre_f, *pre_b, *xcat, *emb, *emit, *hbase;
    cudaGetSymbolAddress((void**)&pre_f, g_pref);
    cudaGetSymbolAddress((void**)&pre_b, g_preb);
    cudaGetSymbolAddress((void**)&xcat,  g_xcat);
    cudaGetSymbolAddress((void**)&emb,   g_emb);
    cudaGetSymbolAddress((void**)&emit,  g_emit);
    cudaGetSymbolAddress((void**)&hbase, g_h);
    int* barp; cudaGetSymbolAddress((void**)&barp, g_bar);
    float* partp; cudaGetSymbolAddress((void**)&partp, g_part);

    dim3 ggrid(16, 64, 2);

    init_kernel<<<32, 256>>>();
    embed_kernel<<<M_, 64>>>(sentence, embed, out_mask);

    gemm_pre<<<ggrid, 256>>>(emb, Wih_0f, Wih_0b, b_0f, b_0b, pre_f, pre_b, E_);
    lstm_layer<<<128, 256, LSTM_SMEM>>>(pre_f, pre_b, Whh_0f, Whh_0b, lengths, xcat,
                                        barp, hbase);

    gemm_pre<<<ggrid, 256>>>(xcat, Wih_1f, Wih_1b, b_1f, b_1b, pre_f, pre_b, 512);
    lstm_layer<<<128, 256, LSTM_SMEM>>>(pre_f, pre_b, Whh_1f, Whh_1b, lengths, xcat,
                                        barp + 2 * T_, hbase + 2 * 2 * H_ * B_);

    emit_kernel<<<M_ / 32, 256>>>(xcat, Wout, bout, emit, out_emit);
    crf_kernel<<<B_, 192>>>(emit, tags, lengths, start_t, end_t, trans, partp);
    finalize_kernel<<<1, 32>>>(out_loss);
    (void)in_sizes; (void)n_in; (void)out_size;
}